// round 11
// baseline (speedup 1.0000x reference)
#include <cuda_runtime.h>

// Problem constants (x[8,512,8192], CHUNK=16, SE 512->64->512)
#define BB   8
#define CC   512
#define LL   8192
#define CS   16
#define NN   (LL / CS)     // 512 chunk positions
#define CH   (CC / 8)      // 64 bottleneck channels
#define NPG  8             // chunk positions per block in the gate kernel

// Static device scratch (no allocs allowed).
__device__ float g_e   [(size_t)BB * CC * NN];   // EMA output, 8 MB
__device__ float g_gate[(size_t)BB * CC * NN];   // gate, 8 MB
__device__ float g_w1t [(size_t)CC * CH];        // w1 transposed [c][o], 128 KB
__device__ float g_w2t [(size_t)CH * CC];        // w2 transposed [k][c], 128 KB

// padded smem index: lane stride becomes 17 banks (conflict-free)
#define SPAD(i) ((i) + ((i) >> 4))

// ---------------------------------------------------------------------------
// Kernel 1: chunked mean pooling + causal EMA per (b, c) row.
// grid = B*C = 4096 blocks, 256 threads. Coalesced; 4-lane shfl chunk sums.
// Blocks 0..127 additionally transpose the SE weights (consumed only by the
// gate kernel, which launches after this kernel completes).
// ---------------------------------------------------------------------------
__global__ void __launch_bounds__(256) pool_ema_kernel(
    const float* __restrict__ x, const float* __restrict__ gamma,
    const float* __restrict__ w1, const float* __restrict__ w2)
{
    const int row = blockIdx.x;            // b*C + c
    const int c   = row & (CC - 1);
    const float g = gamma[c];
    const int t = threadIdx.x;

    // fold in the weight transpose (32768 elems each over 128 blocks)
    if (blockIdx.x < (CC * CH) / 256) {
        const int i = blockIdx.x * 256 + t;
        {   // w1 [CH][CC] -> w1t [CC][CH]
            int o = i / CC, cw = i % CC;
            g_w1t[(size_t)cw * CH + o] = w1[i];
        }
        {   // w2 [CC][CH] -> w2t [CH][CC]
            int cw = i / CH, k = i % CH;
            g_w2t[(size_t)k * CC + cw] = w2[i];
        }
    }

    __shared__ float s[NN + NN / 16];      // padded chunk means

    const float4* xr = reinterpret_cast<const float4*>(x) + (size_t)row * (LL / 4);

    float4 v[8];
#pragma unroll
    for (int k = 0; k < 8; k++)
        v[k] = xr[t + k * 256];            // 8 coalesced LDG.128 in flight

#pragma unroll
    for (int k = 0; k < 8; k++) {
        float r = (v[k].x + v[k].y) + (v[k].z + v[k].w);
        r += __shfl_down_sync(0xffffffffu, r, 2, 4);
        r += __shfl_down_sync(0xffffffffu, r, 1, 4);
        if ((t & 3) == 0) {
            int ci = (t >> 2) + k * 64;    // chunk index 0..511
            s[SPAD(ci)] = r * (1.0f / 16.0f);
        }
    }
    __syncthreads();

    if (t < 32) {
        const int lane = t;
        const float omg = 1.0f - g;

        float y = 0.f;
#pragma unroll
        for (int i = 0; i < 16; i++)
            y = fmaf(g, y, omg * s[lane * 17 + i]);      // SPAD(lane*16+i)
        float Bi = y;
        float g2 = g * g, g4 = g2 * g2, g8 = g4 * g4;
        float Ai = g8 * g8;

#pragma unroll
        for (int off = 1; off < 32; off <<= 1) {
            float a_up = __shfl_up_sync(0xffffffffu, Ai, off);
            float b_up = __shfl_up_sync(0xffffffffu, Bi, off);
            if (lane >= off) {
                Bi = fmaf(Ai, b_up, Bi);
                Ai = Ai * a_up;
            }
        }
        float prefix = __shfl_up_sync(0xffffffffu, Bi, 1);
        if (lane == 0) prefix = 0.f;

        float outv[16];
        y = prefix;
#pragma unroll
        for (int i = 0; i < 16; i++) {
            y = fmaf(g, y, omg * s[lane * 17 + i]);
            outv[i] = y;
        }
        float4* er = reinterpret_cast<float4*>(g_e + (size_t)row * NN + lane * 16);
#pragma unroll
        for (int i = 0; i < 4; i++)
            er[i] = make_float4(outv[4 * i], outv[4 * i + 1], outv[4 * i + 2], outv[4 * i + 3]);
    }
}

// ---------------------------------------------------------------------------
// Kernel 2: SE bottleneck -> sigmoid gate.
// grid (N/NPG = 64, B = 8) = 512 blocks, 512 THREADS (16 warps/block).
// GEMM1 K-dimension is split across 2 thread-halves (256 c each) with a smem
// reduce -> serial chain halved, 2x warps for latency hiding.
// GEMM2: one output channel per thread (no halves loop).
// ---------------------------------------------------------------------------
__global__ void __launch_bounds__(512) se_gate_kernel(
    const float* __restrict__ b1, const float* __restrict__ b2)
{
    const int b  = blockIdx.y;
    const int n0 = blockIdx.x * NPG;
    const int tid = threadIdx.x;

    __shared__ float es[CC][NPG];      // 16 KB e tile
    __shared__ float hp[2][CH][NPG];   // 4 KB partial hidden (then hp[0]=final)

    // ---- load e tile: 1024 float4 / 512 thr = 2 each ----
    const float4* ep = reinterpret_cast<const float4*>(
        g_e + ((size_t)b * CC) * NN + n0);
#pragma unroll
    for (int i = 0; i < 2; i++) {
        int idx = tid + i * 512;                 // = c*2 + q
        int cch = idx >> 1, q = idx & 1;
        float4 v = __ldcs(ep + (size_t)cch * (NN / 4) + q);
        *reinterpret_cast<float4*>(&es[cch][q * 4]) = v;
    }
    __syncthreads();

    // ---- GEMM1 partial: half = tid>>8 covers c in [half*256, half*256+256)
    //      thread (o = (tid&255)>>2, q = tid&3) -> j0 = q*2, 2 positions ----
    {
        const int half = tid >> 8;
        const int o = (tid & 255) >> 2, q = tid & 3;
        const int j0 = q * 2;
        const int c0 = half * 256;
        float a0 = 0.f, a1 = 0.f;
#pragma unroll 8
        for (int cc = c0; cc < c0 + 256; cc++) {
            float w = __ldg(g_w1t + (size_t)cc * CH + o);
            float2 e = *reinterpret_cast<const float2*>(&es[cc][j0]);
            a0 = fmaf(w, e.x, a0);
            a1 = fmaf(w, e.y, a1);
        }
        hp[half][o][j0 + 0] = a0;
        hp[half][o][j0 + 1] = a1;
    }
    __syncthreads();

    // ---- reduce halves + bias + relu (threads 0..255) ----
    if (tid < 256) {
        const int o = tid >> 2, q = tid & 3;
        const int j0 = q * 2;
        const float bb = b1[o];
        float h0 = hp[0][o][j0 + 0] + hp[1][o][j0 + 0] + bb;
        float h1 = hp[0][o][j0 + 1] + hp[1][o][j0 + 1] + bb;
        hp[0][o][j0 + 0] = fmaxf(h0, 0.f);
        hp[0][o][j0 + 1] = fmaxf(h1, 0.f);
    }
    __syncthreads();

    // ---- GEMM2: gate = sigmoid(W2 h + b2), one channel per thread ----
    {
        const int cch = tid;               // 0..511
        float acc[NPG];
#pragma unroll
        for (int j = 0; j < NPG; j++) acc[j] = 0.f;
#pragma unroll 8
        for (int k = 0; k < CH; k++) {
            float w = __ldg(g_w2t + (size_t)k * CC + cch);
            float4 h0 = *reinterpret_cast<const float4*>(&hp[0][k][0]);
            float4 h1 = *reinterpret_cast<const float4*>(&hp[0][k][4]);
            acc[0] = fmaf(w, h0.x, acc[0]); acc[1] = fmaf(w, h0.y, acc[1]);
            acc[2] = fmaf(w, h0.z, acc[2]); acc[3] = fmaf(w, h0.w, acc[3]);
            acc[4] = fmaf(w, h1.x, acc[4]); acc[5] = fmaf(w, h1.y, acc[5]);
            acc[6] = fmaf(w, h1.z, acc[6]); acc[7] = fmaf(w, h1.w, acc[7]);
        }
        const float bb = b2[cch];
        float4 o0, o1;
        o0.x = 1.0f / (1.0f + __expf(-(acc[0] + bb)));
        o0.y = 1.0f / (1.0f + __expf(-(acc[1] + bb)));
        o0.z = 1.0f / (1.0f + __expf(-(acc[2] + bb)));
        o0.w = 1.0f / (1.0f + __expf(-(acc[3] + bb)));
        o1.x = 1.0f / (1.0f + __expf(-(acc[4] + bb)));
        o1.y = 1.0f / (1.0f + __expf(-(acc[5] + bb)));
        o1.z = 1.0f / (1.0f + __expf(-(acc[6] + bb)));
        o1.w = 1.0f / (1.0f + __expf(-(acc[7] + bb)));
        float4* gp = reinterpret_cast<float4*>(
            g_gate + ((size_t)b * CC + cch) * NN + n0);
        gp[0] = o0;
        gp[1] = o1;
    }
}

// ---------------------------------------------------------------------------
// Kernel 3: out = gate * x, barrier-free pure stream.
// grid = 4096 blocks reversed vs pool. Gate distributed via shfl (no smem).
// x read-once (__ldcs), out streaming (__stcs).
// ---------------------------------------------------------------------------
__global__ void __launch_bounds__(256) apply_kernel(
    const float* __restrict__ x, float* __restrict__ out)
{
    const int row  = (BB * CC - 1) - blockIdx.x;      // reversed traversal
    const int t    = threadIdx.x;
    const int warp = t >> 5, lane = t & 31;

    const float* grow = g_gate + (size_t)row * NN;
    const float4* xr  = reinterpret_cast<const float4*>(x)  + (size_t)row * (LL / 4);
    float4*       orr = reinterpret_cast<float4*>(out)      + (size_t)row * (LL / 4);

    float4 v[8];
    float  gk[8];
#pragma unroll
    for (int k = 0; k < 8; k++) {
        v[k]  = __ldcs(xr + t + k * 256);
        gk[k] = grow[warp * 8 + (lane & 7) + k * 64];  // lanes 0..7 hold 8 chunks
    }
#pragma unroll
    for (int k = 0; k < 8; k++) {
        float gv = __shfl_sync(0xffffffffu, gk[k], lane >> 2);
        v[k].x *= gv; v[k].y *= gv; v[k].z *= gv; v[k].w *= gv;
        __stcs(orr + t + k * 256, v[k]);
    }
}

// ---------------------------------------------------------------------------
// kernel_launch: inputs in metadata order: x, gamma, w1, b1, w2, b2
// ---------------------------------------------------------------------------
extern "C" void kernel_launch(void* const* d_in, const int* in_sizes, int n_in,
                              void* d_out, int out_size)
{
    const float* x     = (const float*)d_in[0];
    const float* gamma = (const float*)d_in[1];
    const float* w1    = (const float*)d_in[2];
    const float* b1    = (const float*)d_in[3];
    const float* w2    = (const float*)d_in[4];
    const float* b2    = (const float*)d_in[5];
    float* out = (float*)d_out;

    pool_ema_kernel<<<BB * CC, 256>>>(x, gamma, w1, w2);

    dim3 gridG(NN / NPG, BB);
    se_gate_kernel<<<gridG, 512>>>(b1, b2);

    apply_kernel<<<BB * CC, 256>>>(x, out);
}